// round 6
// baseline (speedup 1.0000x reference)
#include <cuda_runtime.h>

// OrbitalAEVComputer: coefficients [64,256,45] f32 -> out [64,256,4608] f32
// Per (conf,atom): 12 AOVs (4 p + 8 reordered d), radial 12*32, angular 66*8*8.

#define NBLOCKS (64 * 256)
#define OUT_STRIDE 4608
#define NPAIR 66

// cos/sin of shfZ = linspace(0.19634954, 2.94524311, 8)  (odd multiples of pi/16)
__constant__ float COSZ[8] = {
     0.98078528f,  0.83146961f,  0.55557023f,  0.19509032f,
    -0.19509032f, -0.55557023f, -0.83146961f, -0.98078528f
};
__constant__ float SINZ[8] = {
     0.19509032f,  0.55557023f,  0.83146961f,  0.98078528f,
     0.98078528f,  0.83146961f,  0.55557023f,  0.19509032f
};

// triu_indices(12, k=1), i-major
__constant__ unsigned char IU[NPAIR] = {
    0,0,0,0,0,0,0,0,0,0,0,
    1,1,1,1,1,1,1,1,1,1,
    2,2,2,2,2,2,2,2,2,
    3,3,3,3,3,3,3,3,
    4,4,4,4,4,4,4,
    5,5,5,5,5,5,
    6,6,6,6,6,
    7,7,7,7,
    8,8,8,
    9,9,
    10
};
__constant__ unsigned char JU[NPAIR] = {
    1,2,3,4,5,6,7,8,9,10,11,
    2,3,4,5,6,7,8,9,10,11,
    3,4,5,6,7,8,9,10,11,
    4,5,6,7,8,9,10,11,
    5,6,7,8,9,10,11,
    6,7,8,9,10,11,
    7,8,9,10,11,
    8,9,10,11,
    9,10,11,
    10,11,
    11
};

__device__ __forceinline__ void stcs4(float* p, float x, float y, float z, float w)
{
    asm volatile("st.global.cs.v4.f32 [%0], {%1, %2, %3, %4};"
                 :: "l"(p), "f"(x), "f"(y), "f"(z), "f"(w) : "memory");
}

__global__ __launch_bounds__(128, 8)
void orbital_aev_kernel(const float* __restrict__ coeff, float* __restrict__ out)
{
    __shared__ float  dsh[12];
    __shared__ float  nvsh[12][3];
    __shared__ float4 pairsh[NPAIR];   // (cz = 0.95*cos, sz = sqrt(1-cz^2), avdist, 0)

    const int t = threadIdx.x;
    const float* __restrict__ c = coeff + (size_t)blockIdx.x * 45;
    float* __restrict__ o = out + (size_t)blockIdx.x * OUT_STRIDE;

    // ---- Build 12 AOVs: dist + normalized vectors into SMEM ----
    if (t < 12) {
        float x, y, z;
        if (t < 4) {
            int b = 9 + 3 * t;
            x = c[b]; y = c[b + 1]; z = c[b + 2];
        } else {
            int r = (t - 4) >> 1;
            int b = 21 + 6 * r;
            if (((t - 4) & 1) == 0) {        // d row picks [0,2,5]
                x = c[b];     y = c[b + 2]; z = c[b + 5];
            } else {                          // then [4,3,1]
                x = c[b + 4]; y = c[b + 3]; z = c[b + 1];
            }
        }
        float s = x * x + y * y + z * z;
        float inv, d;
        if (s > 1e-24f) { inv = rsqrtf(s); d = s * inv; }
        else            { inv = 0.0f;      d = 0.0f;    }
        dsh[t] = d;
        nvsh[t][0] = x * inv;
        nvsh[t][1] = y * inv;
        nvsh[t][2] = z * inv;
    }
    __syncthreads();

    // ---- Pair terms: cz = 0.95*cos(angle), sz = sqrt(1-cz^2), av = mean dist ----
    if (t < NPAIR) {
        int i = IU[t], j = JU[t];
        float cc = nvsh[i][0] * nvsh[j][0]
                 + nvsh[i][1] * nvsh[j][1]
                 + nvsh[i][2] * nvsh[j][2];
        float cz = 0.95f * cc;
        float sz = sqrtf(fmaxf(0.0f, 1.0f - cz * cz));
        float av = 0.5f * (dsh[i] + dsh[j]);
        pairsh[t] = make_float4(cz, sz, av, 0.0f);
    }

    // ---- Radial: s_aev == r_aev (identical shifts & eta). 384 outputs as 96 STG.128,
    //      lane-contiguous (thread t -> bytes [16t, 16t+16)). ----
    if (t < 96) {
        int aov = t >> 3;
        int q   = t & 7;
        float d  = dsh[aov];
        int   kb = (q & 3) << 2;
        float u0 = d - (0.5f + 0.2f * (float)(kb + 0));
        float u1 = d - (0.5f + 0.2f * (float)(kb + 1));
        float u2 = d - (0.5f + 0.2f * (float)(kb + 2));
        float u3 = d - (0.5f + 0.2f * (float)(kb + 3));
        stcs4(o + (aov << 5) + (q << 2),
              __expf(-16.0f * u0 * u0),
              __expf(-16.0f * u1 * u1),
              __expf(-16.0f * u2 * u2),
              __expf(-16.0f * u3 * u3));
    }
    __syncthreads();

    // ---- Angular: 1056 float4 outputs; float4 q = t + 128*iter is the LANE-FAST dim,
    //      so every STG.128 is 512B contiguous per warp (4 wavefronts, the minimum).
    //      Decode: p = q>>4 (varies), z = (q>>1)&7 (thread-invariant), ahalf = q&1 (invariant).
    const int   zidx  = (t >> 1) & 7;
    const float cosz  = COSZ[zidx];
    const float sinz  = SINZ[zidx];
    const int   ab    = (t & 1) << 2;                 // base shfA index: 0 or 4
    const float a0 = 0.5f + (3.0f / 7.0f) * (float)(ab + 0);
    const float a1 = 0.5f + (3.0f / 7.0f) * (float)(ab + 1);
    const float a2 = 0.5f + (3.0f / 7.0f) * (float)(ab + 2);
    const float a3 = 0.5f + (3.0f / 7.0f) * (float)(ab + 3);

    #pragma unroll
    for (int iter = 0; iter < 9; iter++) {
        int q = t + 128 * iter;
        if (q < 1056) {
            int p = q >> 4;
            float4 cs = pairsh[p];                    // 2-way broadcast LDS.128

            // factor1: cos(angle - shfZ) = cz*cosZ + sqrt(1-cz^2)*sinZ (exact identity)
            float cosd = fmaf(cs.x, cosz, cs.y * sinz);
            float b = fmaf(0.5f, cosd, 0.5f);         // (1+cosd)/2 in [0,1]
            float q2 = b * b;                         // ^2
            q2 *= q2;                                 // ^4
            q2 *= q2;                                 // ^8
            q2 *= q2;                                 // ^16
            q2 *= q2;                                 // ^32
            float g = 2.0f * q2;

            float av = cs.z;
            float u0 = av - a0, u1 = av - a1, u2 = av - a2, u3 = av - a3;
            stcs4(o + 384 + (q << 2),
                  g * __expf(-8.0f * u0 * u0),
                  g * __expf(-8.0f * u1 * u1),
                  g * __expf(-8.0f * u2 * u2),
                  g * __expf(-8.0f * u3 * u3));
        }
    }
}

extern "C" void kernel_launch(void* const* d_in, const int* in_sizes, int n_in,
                              void* d_out, int out_size)
{
    const float* coeff = (const float*)d_in[0];
    float* out = (float*)d_out;
    orbital_aev_kernel<<<NBLOCKS, 128>>>(coeff, out);
}

// round 7
// speedup vs baseline: 1.4004x; 1.4004x over previous
#include <cuda_runtime.h>

// OrbitalAEVComputer: coefficients [64,256,45] f32 -> out [64,256,4608] f32
// Per (conf,atom): 12 AOVs (4 p + 8 reordered d), radial 12*32, angular 66*8*8.

#define NBLOCKS (64 * 256)
#define OUT_STRIDE 4608
#define NPAIR 66

// cos/sin of shfZ = linspace(0.19634954, 2.94524311, 8)  (odd multiples of pi/16)
__constant__ float COSZ[8] = {
     0.98078528f,  0.83146961f,  0.55557023f,  0.19509032f,
    -0.19509032f, -0.55557023f, -0.83146961f, -0.98078528f
};
__constant__ float SINZ[8] = {
     0.19509032f,  0.55557023f,  0.83146961f,  0.98078528f,
     0.98078528f,  0.83146961f,  0.55557023f,  0.19509032f
};

// triu_indices(12, k=1), i-major
__constant__ unsigned char IU[NPAIR] = {
    0,0,0,0,0,0,0,0,0,0,0,
    1,1,1,1,1,1,1,1,1,1,
    2,2,2,2,2,2,2,2,2,
    3,3,3,3,3,3,3,3,
    4,4,4,4,4,4,4,
    5,5,5,5,5,5,
    6,6,6,6,6,
    7,7,7,7,
    8,8,8,
    9,9,
    10
};
__constant__ unsigned char JU[NPAIR] = {
    1,2,3,4,5,6,7,8,9,10,11,
    2,3,4,5,6,7,8,9,10,11,
    3,4,5,6,7,8,9,10,11,
    4,5,6,7,8,9,10,11,
    5,6,7,8,9,10,11,
    6,7,8,9,10,11,
    7,8,9,10,11,
    8,9,10,11,
    9,10,11,
    10,11,
    11
};

// 256-bit store (sm_100+): one instruction writes a full 32B row; lanes at 32B
// stride -> 1024B dense per warp = 8 wavefronts (the minimum).
__device__ __forceinline__ void stg256(float* p,
                                       float v0, float v1, float v2, float v3,
                                       float v4, float v5, float v6, float v7)
{
    asm volatile("st.global.v8.f32 [%0], {%1,%2,%3,%4,%5,%6,%7,%8};"
                 :: "l"(p), "f"(v0), "f"(v1), "f"(v2), "f"(v3),
                           "f"(v4), "f"(v5), "f"(v6), "f"(v7)
                 : "memory");
}

__global__ __launch_bounds__(128, 8)
void orbital_aev_kernel(const float* __restrict__ coeff, float* __restrict__ out)
{
    __shared__ float  dsh[12];
    __shared__ float  nvsh[12][3];
    __shared__ float4 pairsh[NPAIR];   // (cz = 0.95*cos, sz = sqrt(1-cz^2), avdist, 0)

    const int t = threadIdx.x;
    const float* __restrict__ c = coeff + (size_t)blockIdx.x * 45;
    float* __restrict__ o = out + (size_t)blockIdx.x * OUT_STRIDE;

    // ---- Build 12 AOVs: dist + normalized vectors into SMEM ----
    if (t < 12) {
        float x, y, z;
        if (t < 4) {
            int b = 9 + 3 * t;
            x = c[b]; y = c[b + 1]; z = c[b + 2];
        } else {
            int r = (t - 4) >> 1;
            int b = 21 + 6 * r;
            if (((t - 4) & 1) == 0) {        // d row picks [0,2,5]
                x = c[b];     y = c[b + 2]; z = c[b + 5];
            } else {                          // then [4,3,1]
                x = c[b + 4]; y = c[b + 3]; z = c[b + 1];
            }
        }
        float s = x * x + y * y + z * z;
        float inv, d;
        if (s > 1e-24f) { inv = rsqrtf(s); d = s * inv; }
        else            { inv = 0.0f;      d = 0.0f;    }
        dsh[t] = d;
        nvsh[t][0] = x * inv;
        nvsh[t][1] = y * inv;
        nvsh[t][2] = z * inv;
    }
    __syncthreads();

    // ---- Pair terms: cz = 0.95*cos(angle), sz = sqrt(1-cz^2), av = mean dist ----
    if (t < NPAIR) {
        int i = IU[t], j = JU[t];
        float cc = nvsh[i][0] * nvsh[j][0]
                 + nvsh[i][1] * nvsh[j][1]
                 + nvsh[i][2] * nvsh[j][2];
        float cz = 0.95f * cc;
        float sz = sqrtf(fmaxf(0.0f, 1.0f - cz * cz));
        float av = 0.5f * (dsh[i] + dsh[j]);
        pairsh[t] = make_float4(cz, sz, av, 0.0f);
    }

    // ---- Radial: s_aev == r_aev (identical shifts & eta). 384 outputs as 48 STG.256,
    //      thread t<48 owns cols [8q, 8q+8) of aov row (t>>2); shift k = 8*(q&1)+j. ----
    if (t < 48) {
        int aov = t >> 2;
        int q   = t & 3;
        float d  = dsh[aov];
        int   kb = (q & 1) << 3;
        float v[8];
        #pragma unroll
        for (int j = 0; j < 8; j++) {
            float u = d - (0.5f + 0.2f * (float)(kb + j));
            v[j] = __expf(-16.0f * u * u);
        }
        stg256(o + (aov << 5) + (q << 3),
               v[0], v[1], v[2], v[3], v[4], v[5], v[6], v[7]);
    }
    __syncthreads();

    // ---- Angular: 528 row-tasks (pair p, z = m&7 = t&7 thread-invariant).
    //      One pow32 + 8 exps + one STG.256 per task. ----
    const float cosz = COSZ[t & 7];
    const float sinz = SINZ[t & 7];
    #pragma unroll
    for (int iter = 0; iter < 5; iter++) {
        int m = t + 128 * iter;
        if (m < 528) {
            int p = m >> 3;
            float4 cs = pairsh[p];                    // 8-way broadcast LDS.128

            // factor1: cos(angle - shfZ) = cz*cosZ + sqrt(1-cz^2)*sinZ (exact identity)
            float cosd = fmaf(cs.x, cosz, cs.y * sinz);
            float b = fmaf(0.5f, cosd, 0.5f);         // (1+cosd)/2 in [0,1]
            float q2 = b * b;                         // ^2
            q2 *= q2;                                 // ^4
            q2 *= q2;                                 // ^8
            q2 *= q2;                                 // ^16
            q2 *= q2;                                 // ^32
            float g = 2.0f * q2;

            // factor2 for all 8 shfA = 0.5 + (3/7)*a
            float av = cs.z;
            float f2v[8];
            #pragma unroll
            for (int a = 0; a < 8; a++) {
                float ua = av - (0.5f + (3.0f / 7.0f) * (float)a);
                f2v[a] = __expf(-8.0f * ua * ua);
            }

            stg256(o + 384 + (m << 3),
                   g * f2v[0], g * f2v[1], g * f2v[2], g * f2v[3],
                   g * f2v[4], g * f2v[5], g * f2v[6], g * f2v[7]);
        }
    }
}

extern "C" void kernel_launch(void* const* d_in, const int* in_sizes, int n_in,
                              void* d_out, int out_size)
{
    const float* coeff = (const float*)d_in[0];
    float* out = (float*)d_out;
    orbital_aev_kernel<<<NBLOCKS, 128>>>(coeff, out);
}

// round 10
// speedup vs baseline: 1.4581x; 1.0412x over previous
#include <cuda_runtime.h>

// OrbitalAEVComputer: coefficients [64,256,45] f32 -> out [64,256,4608] f32
// Per (conf,atom): 12 AOVs (4 p + 8 reordered d), radial 12*32, angular 66*8*8.

#define NBLOCKS (64 * 256)
#define OUT_STRIDE 4608
#define NPAIR 66

// cos/sin of shfZ = linspace(0.19634954, 2.94524311, 8)  (odd multiples of pi/16)
__constant__ float COSZ[8] = {
     0.98078528f,  0.83146961f,  0.55557023f,  0.19509032f,
    -0.19509032f, -0.55557023f, -0.83146961f, -0.98078528f
};
__constant__ float SINZ[8] = {
     0.19509032f,  0.55557023f,  0.83146961f,  0.98078528f,
     0.98078528f,  0.83146961f,  0.55557023f,  0.19509032f
};

// triu_indices(12, k=1), i-major
__constant__ unsigned char IU[NPAIR] = {
    0,0,0,0,0,0,0,0,0,0,0,
    1,1,1,1,1,1,1,1,1,1,
    2,2,2,2,2,2,2,2,2,
    3,3,3,3,3,3,3,3,
    4,4,4,4,4,4,4,
    5,5,5,5,5,5,
    6,6,6,6,6,
    7,7,7,7,
    8,8,8,
    9,9,
    10
};
__constant__ unsigned char JU[NPAIR] = {
    1,2,3,4,5,6,7,8,9,10,11,
    2,3,4,5,6,7,8,9,10,11,
    3,4,5,6,7,8,9,10,11,
    4,5,6,7,8,9,10,11,
    5,6,7,8,9,10,11,
    6,7,8,9,10,11,
    7,8,9,10,11,
    8,9,10,11,
    9,10,11,
    10,11,
    11
};

// 256-bit store (sm_100+): one instruction writes a full 32B row; lanes at 32B
// stride -> 1024B dense per warp = 8 wavefronts (the minimum).
__device__ __forceinline__ void stg256(float* p,
                                       float v0, float v1, float v2, float v3,
                                       float v4, float v5, float v6, float v7)
{
    asm volatile("st.global.v8.f32 [%0], {%1,%2,%3,%4,%5,%6,%7,%8};"
                 :: "l"(p), "f"(v0), "f"(v1), "f"(v2), "f"(v3),
                           "f"(v4), "f"(v5), "f"(v6), "f"(v7)
                 : "memory");
}

__global__ __launch_bounds__(128, 10)
void orbital_aev_kernel(const float* __restrict__ coeff, float* __restrict__ out)
{
    __shared__ float  dsh[12];
    __shared__ float  nvsh[12][3];
    __shared__ float4 pairsh[NPAIR];   // (cz = 0.95*cos, sz = sqrt(1-cz^2), avdist, 0)

    const int t = threadIdx.x;
    const float* __restrict__ c = coeff + (size_t)blockIdx.x * 45;
    float* __restrict__ o = out + (size_t)blockIdx.x * OUT_STRIDE;

    // ---- Build 12 AOVs: dist + normalized vectors into SMEM ----
    if (t < 12) {
        float x, y, z;
        if (t < 4) {
            int b = 9 + 3 * t;
            x = c[b]; y = c[b + 1]; z = c[b + 2];
        } else {
            int r = (t - 4) >> 1;
            int b = 21 + 6 * r;
            if (((t - 4) & 1) == 0) {        // d row picks [0,2,5]
                x = c[b];     y = c[b + 2]; z = c[b + 5];
            } else {                          // then [4,3,1]
                x = c[b + 4]; y = c[b + 3]; z = c[b + 1];
            }
        }
        float s = x * x + y * y + z * z;
        float inv, d;
        if (s > 1e-24f) { inv = rsqrtf(s); d = s * inv; }
        else            { inv = 0.0f;      d = 0.0f;    }
        dsh[t] = d;
        nvsh[t][0] = x * inv;
        nvsh[t][1] = y * inv;
        nvsh[t][2] = z * inv;
    }
    __syncthreads();

    // ---- Middle phase: DISJOINT thread ranges run concurrently. ----
    // Threads [0,66): pair terms cz/sz/avdist into SMEM.
    // Threads [66,114): radial outputs (s_aev == r_aev; 48 x STG.256).
    if (t < NPAIR) {
        int i = IU[t], j = JU[t];
        float cc = nvsh[i][0] * nvsh[j][0]
                 + nvsh[i][1] * nvsh[j][1]
                 + nvsh[i][2] * nvsh[j][2];
        float cz = 0.95f * cc;
        float sz = sqrtf(fmaxf(0.0f, 1.0f - cz * cz));
        float av = 0.5f * (dsh[i] + dsh[j]);
        pairsh[t] = make_float4(cz, sz, av, 0.0f);
    } else if (t < NPAIR + 48) {
        int r   = t - NPAIR;
        int aov = r >> 2;
        int q   = r & 3;
        float d  = dsh[aov];
        int   kb = (q & 1) << 3;
        float v[8];
        #pragma unroll
        for (int j = 0; j < 8; j++) {
            float u = d - (0.5f + 0.2f * (float)(kb + j));
            v[j] = __expf(-16.0f * u * u);
        }
        stg256(o + (aov << 5) + (q << 3),
               v[0], v[1], v[2], v[3], v[4], v[5], v[6], v[7]);
    }
    __syncthreads();

    // ---- Angular: 528 row-tasks (pair p, z = m&7 = t&7 thread-invariant).
    //      One pow32 + 8 exps + one STG.256 per task. ----
    const float cosz = COSZ[t & 7];
    const float sinz = SINZ[t & 7];
    #pragma unroll
    for (int iter = 0; iter < 5; iter++) {
        int m = t + 128 * iter;
        if (m < 528) {
            int p = m >> 3;
            float4 cs = pairsh[p];                    // 8-way broadcast LDS.128

            // factor1: cos(angle - shfZ) = cz*cosZ + sqrt(1-cz^2)*sinZ (exact identity)
            float cosd = fmaf(cs.x, cosz, cs.y * sinz);
            float b = fmaf(0.5f, cosd, 0.5f);         // (1+cosd)/2 in [0,1]
            float q2 = b * b;                         // ^2
            q2 *= q2;                                 // ^4
            q2 *= q2;                                 // ^8
            q2 *= q2;                                 // ^16
            q2 *= q2;                                 // ^32
            float g = 2.0f * q2;

            // factor2 for all 8 shfA = 0.5 + (3/7)*a
            float av = cs.z;
            float f2v[8];
            #pragma unroll
            for (int a = 0; a < 8; a++) {
                float ua = av - (0.5f + (3.0f / 7.0f) * (float)a);
                f2v[a] = __expf(-8.0f * ua * ua);
            }

            stg256(o + 384 + (m << 3),
                   g * f2v[0], g * f2v[1], g * f2v[2], g * f2v[3],
                   g * f2v[4], g * f2v[5], g * f2v[6], g * f2v[7]);
        }
    }
}

extern "C" void kernel_launch(void* const* d_in, const int* in_sizes, int n_in,
                              void* d_out, int out_size)
{
    const float* coeff = (const float*)d_in[0];
    float* out = (float*)d_out;
    orbital_aev_kernel<<<NBLOCKS, 128>>>(coeff, out);
}